// round 5
// baseline (speedup 1.0000x reference)
#include <cuda_runtime.h>
#include <cstdint>

#define N_NODES 100000
#define N_EDGES 20000
#define NNZ     1000000
#define IN_CH   128
#define OUT_DIM 64

#define NC      (N_EDGES + N_NODES)           // 120000 buckets (edges ++ nodes)
#define SCAN_B  1024
#define NBLK    ((NC + SCAN_B - 1) / SCAN_B)  // 118 (single wave on 148 SMs)

// ---------------------------------------------------------------------------
// Device-global scratch (allocation-free per harness rules)
// ---------------------------------------------------------------------------
__device__ __align__(16) float g_Xl[(size_t)N_NODES * OUT_DIM];  // 25.6 MB
__device__ __align__(16) float g_Xe[(size_t)N_EDGES * OUT_DIM];  // 5.12 MB
__device__ int g_cnt[NC];
__device__ int g_agg[NBLK];      // (block_total << 1) | 1 when published
__device__ int g_off[NC + 1];    // global exclusive offsets
__device__ int g_cur[NC];        // fill cursors
__device__ int g_permA[NNZ];     // bucketed by edge -> vertex id
__device__ int g_permB[NNZ];     // bucketed by node -> edge id

// ---------------------------------------------------------------------------
__device__ __forceinline__ unsigned long long ffma2(unsigned long long a,
                                                    unsigned long long b,
                                                    unsigned long long c) {
    unsigned long long d;
    asm("fma.rn.f32x2 %0, %1, %2, %3;" : "=l"(d) : "l"(a), "l"(b), "l"(c));
    return d;
}
__device__ __forceinline__ float f2lo(unsigned long long v) {
    return __uint_as_float((unsigned)(v & 0xffffffffull));
}
__device__ __forceinline__ float f2hi(unsigned long long v) {
    return __uint_as_float((unsigned)(v >> 32));
}

// ---------------------------------------------------------------------------
// CSR build
// ---------------------------------------------------------------------------
__global__ void k_clear() {
    int t = blockIdx.x * blockDim.x + threadIdx.x;
    if (t < NC) g_cnt[t] = 0;
    if (t < NBLK) g_agg[t] = 0;
    if (t == 0) g_off[NC] = 2 * NNZ;
}

__global__ void k_hist(const int* __restrict__ vertex, const int* __restrict__ edges) {
    int i = blockIdx.x * blockDim.x + threadIdx.x;
    if (i >= NNZ) return;
    atomicAdd(&g_cnt[edges[i]], 1);
    atomicAdd(&g_cnt[N_EDGES + vertex[i]], 1);
}

// Single-launch scan: local Hillis-Steele + decoupled lookback (all blocks
// co-resident in one wave, so per-predecessor spin is deadlock-free & fast).
__global__ __launch_bounds__(SCAN_B) void k_scanall() {
    __shared__ int s[SCAN_B];
    __shared__ int sl[32];
    const int t = threadIdx.x;
    const int b = blockIdx.x;
    const int g = b * SCAN_B + t;

    int val = (g < NC) ? g_cnt[g] : 0;
    s[t] = val;
    __syncthreads();
    int incl = val;
    #pragma unroll
    for (int d = 1; d < SCAN_B; d <<= 1) {
        int x = (t >= d) ? s[t - d] : 0;
        __syncthreads();
        incl += x;
        s[t] = incl;
        __syncthreads();
    }
    // publish this block's aggregate immediately
    if (t == SCAN_B - 1) {
        *(volatile int*)&g_agg[b] = (incl << 1) | 1;
    }

    // parallel lookback: thread t spins on predecessor t (b <= 118 <= 1024)
    int contrib = 0;
    if (t < b) {
        int v;
        do { v = *(volatile int*)&g_agg[t]; } while (!(v & 1));
        contrib = v >> 1;
    }
    // block-reduce contrib -> exclusive prefix for this block
    unsigned mask = 0xffffffffu;
    #pragma unroll
    for (int o = 16; o > 0; o >>= 1) contrib += __shfl_down_sync(mask, contrib, o);
    if ((t & 31) == 0) sl[t >> 5] = contrib;
    __syncthreads();
    if (t < 32) {
        int v2 = sl[t];
        #pragma unroll
        for (int o = 16; o > 0; o >>= 1) v2 += __shfl_down_sync(mask, v2, o);
        if (t == 0) sl[0] = v2;
    }
    __syncthreads();
    int prefix = sl[0];

    if (g < NC) {
        int o = prefix + incl - val;
        g_off[g] = o;
        g_cur[g] = o;
    }
}

__global__ void k_fill(const int* __restrict__ vertex, const int* __restrict__ edges) {
    int i = blockIdx.x * blockDim.x + threadIdx.x;
    if (i >= NNZ) return;
    int e = edges[i];
    int v = vertex[i];
    int pA = atomicAdd(&g_cur[e], 1);
    g_permA[pA] = v;
    int pB = atomicAdd(&g_cur[N_EDGES + v], 1);
    g_permB[pB - NNZ] = e;
}

// ---------------------------------------------------------------------------
// GEMM: g_Xl[N,64] = X[N,128] @ W[128,64]  via packed fma.rn.f32x2.
// Block 256 thr -> tile 128 rows x 64 cols; per-thread 8 rows x 4 cols.
// Xs stored transposed [k][row] so row-pairs load pre-packed (LDS.128).
// Wd stores W duplicated {b,b} so the broadcast operand is pre-packed too.
// ---------------------------------------------------------------------------
__global__ __launch_bounds__(256) void k_gemm(const float* __restrict__ X,
                                              const float* __restrict__ W) {
    __shared__ float Xs[16][136];   // [k][row], stride 136 keeps 16B alignment
    __shared__ float Wd[16][128];   // [k][2*col] duplicated

    const int tid  = threadIdx.x;
    const int row0 = blockIdx.x * 128;
    const int tx   = tid & 15;      // cols 4*tx .. 4*tx+3
    const int ty   = tid >> 4;      // rows 8*ty .. 8*ty+7

    unsigned long long acc[4][4];
    #pragma unroll
    for (int p = 0; p < 4; ++p)
        #pragma unroll
        for (int j = 0; j < 4; ++j) acc[p][j] = 0ull;

    const int sr   = tid >> 1;      // staging row 0..127
    const int sh   = tid & 1;       // staging half (k 0..7 / 8..15)

    for (int kc = 0; kc < 8; ++kc) {
        __syncthreads();
        // stage X chunk transposed
        {
            int grow = row0 + sr;
            #pragma unroll
            for (int q = 0; q < 2; ++q) {
                int kl = sh * 8 + q * 4;
                float4 x = make_float4(0.f, 0.f, 0.f, 0.f);
                if (grow < N_NODES)
                    x = *(const float4*)(X + (size_t)grow * IN_CH + kc * 16 + kl);
                Xs[kl + 0][sr] = x.x;
                Xs[kl + 1][sr] = x.y;
                Xs[kl + 2][sr] = x.z;
                Xs[kl + 3][sr] = x.w;
            }
        }
        // stage W chunk duplicated
        {
            int idx = tid * 4;               // 1024 floats = 16 k x 64 cols
            int kl  = idx >> 6;
            int c   = idx & 63;
            float4 w = *(const float4*)(W + (size_t)(kc * 16 + kl) * OUT_DIM + c);
            float4* dst = (float4*)&Wd[kl][2 * c];
            dst[0] = make_float4(w.x, w.x, w.y, w.y);
            dst[1] = make_float4(w.z, w.z, w.w, w.w);
        }
        __syncthreads();

        #pragma unroll
        for (int k = 0; k < 16; ++k) {
            const float* xr = &Xs[k][8 * ty];
            ulonglong2 a01 = *(const ulonglong2*)xr;        // rows (0,1),(2,3)
            ulonglong2 a23 = *(const ulonglong2*)(xr + 4);  // rows (4,5),(6,7)
            const float* wr = &Wd[k][8 * tx];
            ulonglong2 b01 = *(const ulonglong2*)wr;        // {b0,b0},{b1,b1}
            ulonglong2 b23 = *(const ulonglong2*)(wr + 4);  // {b2,b2},{b3,b3}

            acc[0][0] = ffma2(a01.x, b01.x, acc[0][0]);
            acc[0][1] = ffma2(a01.x, b01.y, acc[0][1]);
            acc[0][2] = ffma2(a01.x, b23.x, acc[0][2]);
            acc[0][3] = ffma2(a01.x, b23.y, acc[0][3]);
            acc[1][0] = ffma2(a01.y, b01.x, acc[1][0]);
            acc[1][1] = ffma2(a01.y, b01.y, acc[1][1]);
            acc[1][2] = ffma2(a01.y, b23.x, acc[1][2]);
            acc[1][3] = ffma2(a01.y, b23.y, acc[1][3]);
            acc[2][0] = ffma2(a23.x, b01.x, acc[2][0]);
            acc[2][1] = ffma2(a23.x, b01.y, acc[2][1]);
            acc[2][2] = ffma2(a23.x, b23.x, acc[2][2]);
            acc[2][3] = ffma2(a23.x, b23.y, acc[2][3]);
            acc[3][0] = ffma2(a23.y, b01.x, acc[3][0]);
            acc[3][1] = ffma2(a23.y, b01.y, acc[3][1]);
            acc[3][2] = ffma2(a23.y, b23.x, acc[3][2]);
            acc[3][3] = ffma2(a23.y, b23.y, acc[3][3]);
        }
    }

    #pragma unroll
    for (int p = 0; p < 4; ++p) {
        int r0 = row0 + 8 * ty + 2 * p;
        if (r0 < N_NODES) {
            float4 lo = make_float4(f2lo(acc[p][0]), f2lo(acc[p][1]),
                                    f2lo(acc[p][2]), f2lo(acc[p][3]));
            *(float4*)(g_Xl + (size_t)r0 * OUT_DIM + 4 * tx) = lo;
        }
        if (r0 + 1 < N_NODES) {
            float4 hi = make_float4(f2hi(acc[p][0]), f2hi(acc[p][1]),
                                    f2hi(acc[p][2]), f2hi(acc[p][3]));
            *(float4*)(g_Xl + (size_t)(r0 + 1) * OUT_DIM + 4 * tx) = hi;
        }
    }
}

// ---------------------------------------------------------------------------
// Gather 1: Xe[e] = (sum Xl[v]) * degE[e] * W_edge[e]
// ---------------------------------------------------------------------------
__global__ __launch_bounds__(256) void k_gatherA(const float* __restrict__ degE,
                                                 const float* __restrict__ W_edge) {
    int t = blockIdx.x * blockDim.x + threadIdx.x;
    int e = t >> 4;
    if (e >= N_EDGES) return;
    int c = (t & 15) << 2;

    int beg = g_off[e];
    int end = g_off[e + 1];

    float4 acc = make_float4(0.f, 0.f, 0.f, 0.f);
    #pragma unroll 4
    for (int j = beg; j < end; ++j) {
        int v = __ldg(&g_permA[j]);
        float4 x = *(const float4*)(g_Xl + (size_t)v * OUT_DIM + c);
        acc.x += x.x; acc.y += x.y; acc.z += x.z; acc.w += x.w;
    }
    float s = degE[e] * W_edge[e];
    acc.x *= s; acc.y *= s; acc.z *= s; acc.w *= s;
    *(float4*)(g_Xe + (size_t)e * OUT_DIM + c) = acc;
}

// ---------------------------------------------------------------------------
// Gather 2: out[v] = (sum Xe[e]) * degV[v]
// ---------------------------------------------------------------------------
__global__ __launch_bounds__(256) void k_gatherB(const float* __restrict__ degV,
                                                 float* __restrict__ out) {
    int t = blockIdx.x * blockDim.x + threadIdx.x;
    int v = t >> 4;
    if (v >= N_NODES) return;
    int c = (t & 15) << 2;

    int beg = g_off[N_EDGES + v] - NNZ;
    int end = g_off[N_EDGES + v + 1] - NNZ;

    float4 acc = make_float4(0.f, 0.f, 0.f, 0.f);
    #pragma unroll 4
    for (int j = beg; j < end; ++j) {
        int e = __ldg(&g_permB[j]);
        float4 x = *(const float4*)(g_Xe + (size_t)e * OUT_DIM + c);
        acc.x += x.x; acc.y += x.y; acc.z += x.z; acc.w += x.w;
    }
    float s = degV[v];
    acc.x *= s; acc.y *= s; acc.z *= s; acc.w *= s;
    *(float4*)(out + (size_t)v * OUT_DIM + c) = acc;
}

// ---------------------------------------------------------------------------
extern "C" void kernel_launch(void* const* d_in, const int* in_sizes, int n_in,
                              void* d_out, int out_size) {
    const float* X      = (const float*)d_in[0];
    const int*   vertex = (const int*)d_in[1];
    const int*   edges  = (const int*)d_in[2];
    const float* W_lin  = (const float*)d_in[3];
    const float* degE   = (const float*)d_in[4];
    const float* degV   = (const float*)d_in[5];
    const float* W_edge = (const float*)d_in[6];
    float*       out    = (float*)d_out;

    // One-time host-side resources (no device memory involved)
    static cudaStream_t s2 = nullptr;
    static cudaEvent_t evFork = nullptr, evJoin = nullptr;
    if (!s2) {
        cudaStreamCreateWithFlags(&s2, cudaStreamNonBlocking);
        cudaEventCreateWithFlags(&evFork, cudaEventDisableTiming);
        cudaEventCreateWithFlags(&evJoin, cudaEventDisableTiming);
    }

    // Fork: GEMM on side stream, CSR build on main stream (independent work)
    cudaEventRecord(evFork, 0);
    cudaStreamWaitEvent(s2, evFork, 0);
    k_gemm<<<(N_NODES + 127) / 128, 256, 0, s2>>>(X, W_lin);
    cudaEventRecord(evJoin, s2);

    k_clear<<<(NC + 255) / 256, 256>>>();
    k_hist<<<(NNZ + 255) / 256, 256>>>(vertex, edges);
    k_scanall<<<NBLK, SCAN_B>>>();
    k_fill<<<(NNZ + 255) / 256, 256>>>(vertex, edges);

    // Join: gathers need both the CSR (main stream) and g_Xl (side stream)
    cudaStreamWaitEvent(0, evJoin, 0);
    k_gatherA<<<(N_EDGES * 16 + 255) / 256, 256>>>(degE, W_edge);
    k_gatherB<<<(N_NODES * 16 + 255) / 256, 256>>>(degV, out);
}

// round 6
// speedup vs baseline: 1.3411x; 1.3411x over previous
#include <cuda_runtime.h>
#include <cstdint>

#define N_NODES 100000
#define N_EDGES 20000
#define NNZ     1000000
#define IN_CH   128
#define OUT_DIM 64

#define NC      (N_EDGES + N_NODES)       // 120000 concatenated buckets
#define SCAN_B  1024
#define NBLK    ((NC + SCAN_B - 1) / SCAN_B)  // 118

// ---------------------------------------------------------------------------
// Device-global scratch (allocation-free per harness rules)
// ---------------------------------------------------------------------------
__device__ __align__(16) float g_Xl[(size_t)N_NODES * OUT_DIM];  // 25.6 MB
__device__ __align__(16) float g_Xe[(size_t)N_EDGES * OUT_DIM];  // 5.12 MB
__device__ int g_cnt[NC];
__device__ int g_offp[NC];
__device__ int g_bsum[NBLK];
__device__ int g_boff[NBLK];
__device__ int g_off[NC + 1];
__device__ int g_cur[NC];
__device__ int g_permA[NNZ];     // bucketed by edge -> vertex id
__device__ int g_permB[NNZ];     // bucketed by node -> edge id

// ---------------------------------------------------------------------------
typedef unsigned long long ull;

__device__ __forceinline__ ull ffma2(ull a, ull b, ull c) {
    ull d;
    asm("fma.rn.f32x2 %0, %1, %2, %3;" : "=l"(d) : "l"(a), "l"(b), "l"(c));
    return d;
}
__device__ __forceinline__ ull dup2(float x) {
    ull r;
    asm("mov.b64 %0, {%1, %1};" : "=l"(r) : "f"(x));
    return r;
}

// ---------------------------------------------------------------------------
// CSR build (identical to R4 known-good)
// ---------------------------------------------------------------------------
__global__ void k_clear() {
    int t = blockIdx.x * blockDim.x + threadIdx.x;
    if (t < NC) g_cnt[t] = 0;
}

__global__ void k_hist(const int* __restrict__ vertex, const int* __restrict__ edges) {
    int i = blockIdx.x * blockDim.x + threadIdx.x;
    if (i >= NNZ) return;
    atomicAdd(&g_cnt[edges[i]], 1);
    atomicAdd(&g_cnt[N_EDGES + vertex[i]], 1);
}

__global__ __launch_bounds__(SCAN_B) void k_scan1() {
    __shared__ int s[SCAN_B];
    int t = threadIdx.x;
    int g = blockIdx.x * SCAN_B + t;
    int val = (g < NC) ? g_cnt[g] : 0;
    s[t] = val;
    __syncthreads();
    int incl = val;
    #pragma unroll
    for (int d = 1; d < SCAN_B; d <<= 1) {
        int x = (t >= d) ? s[t - d] : 0;
        __syncthreads();
        incl += x;
        s[t] = incl;
        __syncthreads();
    }
    if (g < NC) g_offp[g] = incl - val;
    if (t == SCAN_B - 1) g_bsum[blockIdx.x] = incl;
}

__global__ __launch_bounds__(128) void k_scan2() {
    __shared__ int s[128];
    int t = threadIdx.x;
    int val = (t < NBLK) ? g_bsum[t] : 0;
    s[t] = val;
    __syncthreads();
    int incl = val;
    #pragma unroll
    for (int d = 1; d < 128; d <<= 1) {
        int x = (t >= d) ? s[t - d] : 0;
        __syncthreads();
        incl += x;
        s[t] = incl;
        __syncthreads();
    }
    if (t < NBLK) g_boff[t] = incl - val;
}

__global__ void k_scan3() {
    int g = blockIdx.x * blockDim.x + threadIdx.x;
    if (g < NC) {
        int o = g_offp[g] + g_boff[g / SCAN_B];
        g_off[g] = o;
        g_cur[g] = o;
    }
    if (g == 0) g_off[NC] = 2 * NNZ;
}

__global__ void k_fill(const int* __restrict__ vertex, const int* __restrict__ edges) {
    int i = blockIdx.x * blockDim.x + threadIdx.x;
    if (i >= NNZ) return;
    int e = edges[i];
    int v = vertex[i];
    int pA = atomicAdd(&g_cur[e], 1);
    g_permA[pA] = v;
    int pB = atomicAdd(&g_cur[N_EDGES + v], 1);
    g_permB[pB - NNZ] = e;
}

// ---------------------------------------------------------------------------
// GEMM: g_Xl[N,64] = X[N,128] @ W[128,64] via fma.rn.f32x2.
// 256 threads, tile 256 rows x 64 cols, per-thread 8 rows x 8 cols.
// Xs transposed [k][row]; Ws natural [k][col] (column PAIRS feed FFMA2's b).
// Row operand duplicated {x,x} in registers (ALU pipe) -> 1 B smem / FMA.
// ---------------------------------------------------------------------------
__global__ __launch_bounds__(256, 2) void k_gemm(const float* __restrict__ X,
                                                 const float* __restrict__ W) {
    __shared__ float Xs[16][264];   // [k][row], stride 264 (16B-aligned rows)
    __shared__ float Ws[16][64];    // [k][col]

    const int tid  = threadIdx.x;
    const int row0 = blockIdx.x * 256;
    const int tx   = tid & 7;       // cols 8*tx .. 8*tx+7
    const int ty   = tid >> 3;      // rows 8*ty .. 8*ty+7 (ty 0..31)

    ull acc[8][4];                  // [row][col-pair]
    #pragma unroll
    for (int r = 0; r < 8; ++r)
        #pragma unroll
        for (int cp = 0; cp < 4; ++cp) acc[r][cp] = 0ull;

    for (int kc = 0; kc < 8; ++kc) {
        __syncthreads();
        // Stage X chunk transposed: thread owns one row, 16 k-values
        {
            int grow = row0 + tid;
            #pragma unroll
            for (int q = 0; q < 4; ++q) {
                float4 x = make_float4(0.f, 0.f, 0.f, 0.f);
                if (grow < N_NODES)
                    x = *(const float4*)(X + (size_t)grow * IN_CH + kc * 16 + q * 4);
                Xs[q * 4 + 0][tid] = x.x;
                Xs[q * 4 + 1][tid] = x.y;
                Xs[q * 4 + 2][tid] = x.z;
                Xs[q * 4 + 3][tid] = x.w;
            }
        }
        // Stage W chunk natural: 16k x 64c = 1024 floats, one float4/thread
        {
            int idx = tid * 4;
            int kl  = idx >> 6;
            int c   = idx & 63;
            *(float4*)&Ws[kl][c] =
                *(const float4*)(W + (size_t)(kc * 16 + kl) * OUT_DIM + c);
        }
        __syncthreads();

        #pragma unroll
        for (int k = 0; k < 16; ++k) {
            float4 xa = *(const float4*)&Xs[k][8 * ty];       // rows 0..3
            float4 xb = *(const float4*)&Xs[k][8 * ty + 4];   // rows 4..7
            ulonglong2 wA = *(const ulonglong2*)&Ws[k][8 * tx];      // (c0,c1),(c2,c3)
            ulonglong2 wB = *(const ulonglong2*)&Ws[k][8 * tx + 4];  // (c4,c5),(c6,c7)

            ull d[8];
            d[0] = dup2(xa.x); d[1] = dup2(xa.y); d[2] = dup2(xa.z); d[3] = dup2(xa.w);
            d[4] = dup2(xb.x); d[5] = dup2(xb.y); d[6] = dup2(xb.z); d[7] = dup2(xb.w);

            #pragma unroll
            for (int r = 0; r < 8; ++r) {
                acc[r][0] = ffma2(d[r], wA.x, acc[r][0]);
                acc[r][1] = ffma2(d[r], wA.y, acc[r][1]);
                acc[r][2] = ffma2(d[r], wB.x, acc[r][2]);
                acc[r][3] = ffma2(d[r], wB.y, acc[r][3]);
            }
        }
    }

    // Store: each acc[r] holds 8 consecutive cols as 4 packed pairs.
    #pragma unroll
    for (int r = 0; r < 8; ++r) {
        int grow = row0 + 8 * ty + r;
        if (grow < N_NODES) {
            float* dst = g_Xl + (size_t)grow * OUT_DIM + 8 * tx;
            ulonglong2 lo; lo.x = acc[r][0]; lo.y = acc[r][1];
            ulonglong2 hi; hi.x = acc[r][2]; hi.y = acc[r][3];
            *(ulonglong2*)dst       = lo;
            *(ulonglong2*)(dst + 4) = hi;
        }
    }
}

// ---------------------------------------------------------------------------
// Gather 1: Xe[e] = (sum Xl[v]) * degE[e] * W_edge[e]
// ---------------------------------------------------------------------------
__global__ __launch_bounds__(256) void k_gatherA(const float* __restrict__ degE,
                                                 const float* __restrict__ W_edge) {
    int t = blockIdx.x * blockDim.x + threadIdx.x;
    int e = t >> 4;
    if (e >= N_EDGES) return;
    int c = (t & 15) << 2;

    int beg = g_off[e];
    int end = g_off[e + 1];

    float4 acc = make_float4(0.f, 0.f, 0.f, 0.f);
    #pragma unroll 4
    for (int j = beg; j < end; ++j) {
        int v = __ldg(&g_permA[j]);
        float4 x = *(const float4*)(g_Xl + (size_t)v * OUT_DIM + c);
        acc.x += x.x; acc.y += x.y; acc.z += x.z; acc.w += x.w;
    }
    float s = degE[e] * W_edge[e];
    acc.x *= s; acc.y *= s; acc.z *= s; acc.w *= s;
    *(float4*)(g_Xe + (size_t)e * OUT_DIM + c) = acc;
}

// ---------------------------------------------------------------------------
// Gather 2: out[v] = (sum Xe[e]) * degV[v]
// ---------------------------------------------------------------------------
__global__ __launch_bounds__(256) void k_gatherB(const float* __restrict__ degV,
                                                 float* __restrict__ out) {
    int t = blockIdx.x * blockDim.x + threadIdx.x;
    int v = t >> 4;
    if (v >= N_NODES) return;
    int c = (t & 15) << 2;

    int beg = g_off[N_EDGES + v] - NNZ;
    int end = g_off[N_EDGES + v + 1] - NNZ;

    float4 acc = make_float4(0.f, 0.f, 0.f, 0.f);
    #pragma unroll 4
    for (int j = beg; j < end; ++j) {
        int e = __ldg(&g_permB[j]);
        float4 x = *(const float4*)(g_Xe + (size_t)e * OUT_DIM + c);
        acc.x += x.x; acc.y += x.y; acc.z += x.z; acc.w += x.w;
    }
    float s = degV[v];
    acc.x *= s; acc.y *= s; acc.z *= s; acc.w *= s;
    *(float4*)(out + (size_t)v * OUT_DIM + c) = acc;
}

// ---------------------------------------------------------------------------
extern "C" void kernel_launch(void* const* d_in, const int* in_sizes, int n_in,
                              void* d_out, int out_size) {
    const float* X      = (const float*)d_in[0];
    const int*   vertex = (const int*)d_in[1];
    const int*   edges  = (const int*)d_in[2];
    const float* W_lin  = (const float*)d_in[3];
    const float* degE   = (const float*)d_in[4];
    const float* degV   = (const float*)d_in[5];
    const float* W_edge = (const float*)d_in[6];
    float*       out    = (float*)d_out;

    k_clear<<<(NC + 255) / 256, 256>>>();
    k_hist<<<(NNZ + 255) / 256, 256>>>(vertex, edges);
    k_scan1<<<NBLK, SCAN_B>>>();
    k_scan2<<<1, 128>>>();
    k_scan3<<<(NC + 255) / 256, 256>>>();
    k_fill<<<(NNZ + 255) / 256, 256>>>(vertex, edges);
    k_gemm<<<(N_NODES + 255) / 256, 256>>>(X, W_lin);
    k_gatherA<<<(N_EDGES * 16 + 255) / 256, 256>>>(degE, W_edge);
    k_gatherB<<<(N_NODES * 16 + 255) / 256, 256>>>(degV, out);
}

// round 7
// speedup vs baseline: 1.6369x; 1.2205x over previous
#include <cuda_runtime.h>
#include <cuda_fp16.h>
#include <cstdint>

#define N_NODES 100000
#define N_EDGES 20000
#define NNZ     1000000
#define IN_CH   128
#define OUT_DIM 64

#define NC      (N_EDGES + N_NODES)       // 120000 concatenated buckets
#define SCAN_B  1024
#define NBLK    ((NC + SCAN_B - 1) / SCAN_B)  // 118

// ---------------------------------------------------------------------------
// Device-global scratch (allocation-free per harness rules)
// ---------------------------------------------------------------------------
__device__ __align__(16) unsigned short g_Xl16[(size_t)N_NODES * OUT_DIM]; // 12.8 MB fp16
__device__ __align__(16) unsigned short g_Xe16[(size_t)N_EDGES * OUT_DIM]; // 2.56 MB fp16
__device__ int g_cnt[NC];        // zero at start of every run (reset by gathers)
__device__ int g_offp[NC];
__device__ int g_bsum[NBLK];
__device__ int g_off[NC + 1];
__device__ int g_cur[NC];
__device__ int g_permA[NNZ];     // bucketed by edge -> vertex id
__device__ int g_permB[NNZ];     // bucketed by node -> edge id

// ---------------------------------------------------------------------------
// CSR build
// ---------------------------------------------------------------------------
__global__ void k_hist(const int* __restrict__ vertex, const int* __restrict__ edges) {
    int i = blockIdx.x * blockDim.x + threadIdx.x;
    if (i >= NNZ) return;
    atomicAdd(&g_cnt[edges[i]], 1);
    atomicAdd(&g_cnt[N_EDGES + vertex[i]], 1);
}

__global__ __launch_bounds__(SCAN_B) void k_scan1() {
    __shared__ int s[SCAN_B];
    int t = threadIdx.x;
    int g = blockIdx.x * SCAN_B + t;
    int val = (g < NC) ? g_cnt[g] : 0;
    s[t] = val;
    __syncthreads();
    int incl = val;
    #pragma unroll
    for (int d = 1; d < SCAN_B; d <<= 1) {
        int x = (t >= d) ? s[t - d] : 0;
        __syncthreads();
        incl += x;
        s[t] = incl;
        __syncthreads();
    }
    if (g < NC) g_offp[g] = incl - val;
    if (t == SCAN_B - 1) g_bsum[blockIdx.x] = incl;
}

// Fused scan2+scan3: each block recomputes the block-level exclusive prefix
// (118 entries) with a block reduce, then emits final offsets + cursors.
__global__ __launch_bounds__(SCAN_B) void k_scan23() {
    __shared__ int sl[32];
    const int t = threadIdx.x;
    const int b = blockIdx.x;

    int val = (t < NBLK && t < b) ? g_bsum[t] : 0;
    unsigned m = 0xffffffffu;
    #pragma unroll
    for (int o = 16; o > 0; o >>= 1) val += __shfl_down_sync(m, val, o);
    if ((t & 31) == 0) sl[t >> 5] = val;
    __syncthreads();
    if (t < 32) {
        int v = sl[t];
        #pragma unroll
        for (int o = 16; o > 0; o >>= 1) v += __shfl_down_sync(m, v, o);
        if (t == 0) sl[0] = v;
    }
    __syncthreads();
    const int prefix = sl[0];

    int g = b * SCAN_B + t;
    if (g < NC) {
        int o = g_offp[g] + prefix;
        g_off[g] = o;
        g_cur[g] = o;
    }
    if (b == 0 && t == 0) g_off[NC] = 2 * NNZ;
}

__global__ void k_fill(const int* __restrict__ vertex, const int* __restrict__ edges) {
    int i = blockIdx.x * blockDim.x + threadIdx.x;
    if (i >= NNZ) return;
    int e = edges[i];
    int v = vertex[i];
    int pA = atomicAdd(&g_cur[e], 1);
    g_permA[pA] = v;
    int pB = atomicAdd(&g_cur[N_EDGES + v], 1);
    g_permB[pB - NNZ] = e;
}

// ---------------------------------------------------------------------------
// GEMM (R4-proven): Xl[N,64] = X[N,128] @ W[128,64], fp32 compute, fp16 store.
// ---------------------------------------------------------------------------
__global__ __launch_bounds__(256) void k_gemm(const float* __restrict__ X,
                                              const float* __restrict__ W) {
    __shared__ float Ws[IN_CH][OUT_DIM];  // [k][col], 32 KB
    __shared__ float Xs[32][68];          // [k][row], padded

    const int tid  = threadIdx.x;
    const int row0 = blockIdx.x * 64;

    {
        const float4* W4  = (const float4*)W;
        float4*       Ws4 = (float4*)&Ws[0][0];
        #pragma unroll
        for (int i = tid; i < IN_CH * OUT_DIM / 4; i += 256) Ws4[i] = W4[i];
    }

    const int tx = tid & 15;
    const int ty = tid >> 4;

    float acc[4][4];
    #pragma unroll
    for (int i = 0; i < 4; ++i)
        #pragma unroll
        for (int j = 0; j < 4; ++j) acc[i][j] = 0.0f;

    const int lr  = tid >> 3;
    const int lkf = tid & 7;

    for (int kc = 0; kc < 4; ++kc) {
        __syncthreads();
        #pragma unroll
        for (int j = 0; j < 2; ++j) {
            int r    = lr + 32 * j;
            int grow = row0 + r;
            float4 x = make_float4(0.f, 0.f, 0.f, 0.f);
            if (grow < N_NODES)
                x = *(const float4*)(X + (size_t)grow * IN_CH + kc * 32 + lkf * 4);
            Xs[lkf * 4 + 0][r] = x.x;
            Xs[lkf * 4 + 1][r] = x.y;
            Xs[lkf * 4 + 2][r] = x.z;
            Xs[lkf * 4 + 3][r] = x.w;
        }
        __syncthreads();

        #pragma unroll
        for (int k = 0; k < 32; ++k) {
            float4 a = *(const float4*)&Xs[k][4 * ty];
            float4 b = *(const float4*)&Ws[kc * 32 + k][4 * tx];
            acc[0][0] += a.x * b.x; acc[0][1] += a.x * b.y;
            acc[0][2] += a.x * b.z; acc[0][3] += a.x * b.w;
            acc[1][0] += a.y * b.x; acc[1][1] += a.y * b.y;
            acc[1][2] += a.y * b.z; acc[1][3] += a.y * b.w;
            acc[2][0] += a.z * b.x; acc[2][1] += a.z * b.y;
            acc[2][2] += a.z * b.z; acc[2][3] += a.z * b.w;
            acc[3][0] += a.w * b.x; acc[3][1] += a.w * b.y;
            acc[3][2] += a.w * b.z; acc[3][3] += a.w * b.w;
        }
    }

    #pragma unroll
    for (int i = 0; i < 4; ++i) {
        int grow = row0 + 4 * ty + i;
        if (grow < N_NODES) {
            __half2 h01 = __floats2half2_rn(acc[i][0], acc[i][1]);
            __half2 h23 = __floats2half2_rn(acc[i][2], acc[i][3]);
            uint2 u = make_uint2(*reinterpret_cast<unsigned*>(&h01),
                                 *reinterpret_cast<unsigned*>(&h23));
            *(uint2*)(g_Xl16 + (size_t)grow * OUT_DIM + 4 * tx) = u;
        }
    }
}

// ---------------------------------------------------------------------------
// Gather 1: Xe[e] = (sum Xl[v]) * degE[e] * W_edge[e].  fp16 in/out, fp32 acc.
// 8 threads/edge, each owns 8 cols (one uint4 = 8 halves).
// Also resets g_cnt[e] for the next graph replay.
// ---------------------------------------------------------------------------
__global__ __launch_bounds__(256) void k_gatherA(const float* __restrict__ degE,
                                                 const float* __restrict__ W_edge) {
    int t = blockIdx.x * blockDim.x + threadIdx.x;
    int e = t >> 3;
    if (e >= N_EDGES) return;
    int lane = t & 7;
    int c = lane << 3;

    if (lane == 0) g_cnt[e] = 0;   // reset for next replay

    int beg = g_off[e];
    int end = g_off[e + 1];

    float a0 = 0.f, a1 = 0.f, a2 = 0.f, a3 = 0.f;
    float a4 = 0.f, a5 = 0.f, a6 = 0.f, a7 = 0.f;
    #pragma unroll 4
    for (int j = beg; j < end; ++j) {
        int v = __ldg(&g_permA[j]);
        uint4 u = *(const uint4*)(g_Xl16 + (size_t)v * OUT_DIM + c);
        float2 f0 = __half22float2(*reinterpret_cast<__half2*>(&u.x));
        float2 f1 = __half22float2(*reinterpret_cast<__half2*>(&u.y));
        float2 f2 = __half22float2(*reinterpret_cast<__half2*>(&u.z));
        float2 f3 = __half22float2(*reinterpret_cast<__half2*>(&u.w));
        a0 += f0.x; a1 += f0.y; a2 += f1.x; a3 += f1.y;
        a4 += f2.x; a5 += f2.y; a6 += f3.x; a7 += f3.y;
    }
    float s = degE[e] * W_edge[e];
    __half2 h0 = __floats2half2_rn(a0 * s, a1 * s);
    __half2 h1 = __floats2half2_rn(a2 * s, a3 * s);
    __half2 h2 = __floats2half2_rn(a4 * s, a5 * s);
    __half2 h3 = __floats2half2_rn(a6 * s, a7 * s);
    uint4 o;
    o.x = *reinterpret_cast<unsigned*>(&h0);
    o.y = *reinterpret_cast<unsigned*>(&h1);
    o.z = *reinterpret_cast<unsigned*>(&h2);
    o.w = *reinterpret_cast<unsigned*>(&h3);
    *(uint4*)(g_Xe16 + (size_t)e * OUT_DIM + c) = o;
}

// ---------------------------------------------------------------------------
// Gather 2: out[v] = (sum Xe[e]) * degV[v].  fp16 in, fp32 out.
// Also resets g_cnt[N_EDGES+v] for the next graph replay.
// ---------------------------------------------------------------------------
__global__ __launch_bounds__(256) void k_gatherB(const float* __restrict__ degV,
                                                 float* __restrict__ out) {
    int t = blockIdx.x * blockDim.x + threadIdx.x;
    int v = t >> 3;
    if (v >= N_NODES) return;
    int lane = t & 7;
    int c = lane << 3;

    if (lane == 0) g_cnt[N_EDGES + v] = 0;   // reset for next replay

    int beg = g_off[N_EDGES + v] - NNZ;
    int end = g_off[N_EDGES + v + 1] - NNZ;

    float a0 = 0.f, a1 = 0.f, a2 = 0.f, a3 = 0.f;
    float a4 = 0.f, a5 = 0.f, a6 = 0.f, a7 = 0.f;
    #pragma unroll 4
    for (int j = beg; j < end; ++j) {
        int e = __ldg(&g_permB[j]);
        uint4 u = *(const uint4*)(g_Xe16 + (size_t)e * OUT_DIM + c);
        float2 f0 = __half22float2(*reinterpret_cast<__half2*>(&u.x));
        float2 f1 = __half22float2(*reinterpret_cast<__half2*>(&u.y));
        float2 f2 = __half22float2(*reinterpret_cast<__half2*>(&u.z));
        float2 f3 = __half22float2(*reinterpret_cast<__half2*>(&u.w));
        a0 += f0.x; a1 += f0.y; a2 += f1.x; a3 += f1.y;
        a4 += f2.x; a5 += f2.y; a6 += f3.x; a7 += f3.y;
    }
    float s = degV[v];
    float* dst = out + (size_t)v * OUT_DIM + c;
    *(float4*)dst       = make_float4(a0 * s, a1 * s, a2 * s, a3 * s);
    *(float4*)(dst + 4) = make_float4(a4 * s, a5 * s, a6 * s, a7 * s);
}

// ---------------------------------------------------------------------------
extern "C" void kernel_launch(void* const* d_in, const int* in_sizes, int n_in,
                              void* d_out, int out_size) {
    const float* X      = (const float*)d_in[0];
    const int*   vertex = (const int*)d_in[1];
    const int*   edges  = (const int*)d_in[2];
    const float* W_lin  = (const float*)d_in[3];
    const float* degE   = (const float*)d_in[4];
    const float* degV   = (const float*)d_in[5];
    const float* W_edge = (const float*)d_in[6];
    float*       out    = (float*)d_out;

    // g_cnt starts zeroed (static init on first run; gather kernels re-zero
    // it at the end of every run, so each graph replay sees zeros).
    k_hist<<<(NNZ + 255) / 256, 256>>>(vertex, edges);
    k_scan1<<<NBLK, SCAN_B>>>();
    k_scan23<<<NBLK, SCAN_B>>>();
    k_fill<<<(NNZ + 255) / 256, 256>>>(vertex, edges);
    k_gemm<<<(N_NODES + 63) / 64, 256>>>(X, W_lin);
    k_gatherA<<<(N_EDGES * 8 + 255) / 256, 256>>>(degE, W_edge);
    k_gatherB<<<(N_NODES * 8 + 255) / 256, 256>>>(degV, out);
}

// round 8
// speedup vs baseline: 1.7193x; 1.0504x over previous
#include <cuda_runtime.h>
#include <cuda_fp16.h>
#include <cstdint>

#define N_NODES 100000
#define N_EDGES 20000
#define NNZ     1000000
#define IN_CH   128
#define OUT_DIM 64

#define RA 4                               // edge-cursor replicas
#define RB 2                               // node-cursor replicas
#define EBASE (N_EDGES * RA)               // 80000: start of node section
#define NC2   (N_EDGES * RA + N_NODES * RB) // 280000 scanned counters
#define SCAN_B 1024
#define NBLK  ((NC2 + SCAN_B - 1) / SCAN_B) // 274

// ---------------------------------------------------------------------------
// Device-global scratch (allocation-free per harness rules)
// ---------------------------------------------------------------------------
__device__ __align__(16) unsigned short g_Xl16[(size_t)N_NODES * OUT_DIM]; // 12.8 MB
__device__ __align__(16) unsigned short g_Xe16[(size_t)N_EDGES * OUT_DIM]; // 2.56 MB
__device__ int g_cnt[NC2];       // zero at start of every run (reset by gathers)
__device__ int g_offp[NC2];
__device__ int g_bsum[NBLK];
__device__ int g_off[NC2 + 1];
__device__ int g_cur[NC2];
__device__ int g_permA[NNZ];     // bucketed by edge -> vertex id
__device__ int g_permB[NNZ];     // bucketed by node -> edge id

// ---------------------------------------------------------------------------
// CSR build with replicated cursors
// ---------------------------------------------------------------------------
__global__ void k_hist(const int* __restrict__ vertex, const int* __restrict__ edges) {
    int i = blockIdx.x * blockDim.x + threadIdx.x;
    if (i >= NNZ) return;
    int w  = i >> 5;                 // warp-varying replica pick
    int ra = w & (RA - 1);
    int rb = w & (RB - 1);
    atomicAdd(&g_cnt[edges[i] * RA + ra], 1);
    atomicAdd(&g_cnt[EBASE + vertex[i] * RB + rb], 1);
}

__global__ __launch_bounds__(SCAN_B) void k_scan1() {
    __shared__ int s[SCAN_B];
    int t = threadIdx.x;
    int g = blockIdx.x * SCAN_B + t;
    int val = (g < NC2) ? g_cnt[g] : 0;
    s[t] = val;
    __syncthreads();
    int incl = val;
    #pragma unroll
    for (int d = 1; d < SCAN_B; d <<= 1) {
        int x = (t >= d) ? s[t - d] : 0;
        __syncthreads();
        incl += x;
        s[t] = incl;
        __syncthreads();
    }
    if (g < NC2) g_offp[g] = incl - val;
    if (t == SCAN_B - 1) g_bsum[blockIdx.x] = incl;
}

// Fused scan2+scan3: each block reduces the block-aggregate prefix itself.
__global__ __launch_bounds__(SCAN_B) void k_scan23() {
    __shared__ int sl[32];
    const int t = threadIdx.x;
    const int b = blockIdx.x;

    int val = (t < NBLK && t < b) ? g_bsum[t] : 0;
    unsigned m = 0xffffffffu;
    #pragma unroll
    for (int o = 16; o > 0; o >>= 1) val += __shfl_down_sync(m, val, o);
    if ((t & 31) == 0) sl[t >> 5] = val;
    __syncthreads();
    if (t < 32) {
        int v = sl[t];
        #pragma unroll
        for (int o = 16; o > 0; o >>= 1) v += __shfl_down_sync(m, v, o);
        if (t == 0) sl[0] = v;
    }
    __syncthreads();
    const int prefix = sl[0];

    int g = b * SCAN_B + t;
    if (g < NC2) {
        int o = g_offp[g] + prefix;
        g_off[g] = o;
        g_cur[g] = o;
    }
    if (b == 0 && t == 0) g_off[NC2] = 2 * NNZ;
}

__global__ void k_fill(const int* __restrict__ vertex, const int* __restrict__ edges) {
    int i = blockIdx.x * blockDim.x + threadIdx.x;
    if (i >= NNZ) return;
    int w  = i >> 5;
    int ra = w & (RA - 1);
    int rb = w & (RB - 1);
    int e = edges[i];
    int v = vertex[i];
    int pA = atomicAdd(&g_cur[e * RA + ra], 1);
    g_permA[pA] = v;
    int pB = atomicAdd(&g_cur[EBASE + v * RB + rb], 1);
    g_permB[pB - NNZ] = e;
}

// ---------------------------------------------------------------------------
// GEMM (R4-proven): Xl[N,64] = X[N,128] @ W[128,64], fp32 compute, fp16 store.
// ---------------------------------------------------------------------------
__global__ __launch_bounds__(256) void k_gemm(const float* __restrict__ X,
                                              const float* __restrict__ W) {
    __shared__ float Ws[IN_CH][OUT_DIM];
    __shared__ float Xs[32][68];

    const int tid  = threadIdx.x;
    const int row0 = blockIdx.x * 64;

    {
        const float4* W4  = (const float4*)W;
        float4*       Ws4 = (float4*)&Ws[0][0];
        #pragma unroll
        for (int i = tid; i < IN_CH * OUT_DIM / 4; i += 256) Ws4[i] = W4[i];
    }

    const int tx = tid & 15;
    const int ty = tid >> 4;

    float acc[4][4];
    #pragma unroll
    for (int i = 0; i < 4; ++i)
        #pragma unroll
        for (int j = 0; j < 4; ++j) acc[i][j] = 0.0f;

    const int lr  = tid >> 3;
    const int lkf = tid & 7;

    for (int kc = 0; kc < 4; ++kc) {
        __syncthreads();
        #pragma unroll
        for (int j = 0; j < 2; ++j) {
            int r    = lr + 32 * j;
            int grow = row0 + r;
            float4 x = make_float4(0.f, 0.f, 0.f, 0.f);
            if (grow < N_NODES)
                x = *(const float4*)(X + (size_t)grow * IN_CH + kc * 32 + lkf * 4);
            Xs[lkf * 4 + 0][r] = x.x;
            Xs[lkf * 4 + 1][r] = x.y;
            Xs[lkf * 4 + 2][r] = x.z;
            Xs[lkf * 4 + 3][r] = x.w;
        }
        __syncthreads();

        #pragma unroll
        for (int k = 0; k < 32; ++k) {
            float4 a = *(const float4*)&Xs[k][4 * ty];
            float4 b = *(const float4*)&Ws[kc * 32 + k][4 * tx];
            acc[0][0] += a.x * b.x; acc[0][1] += a.x * b.y;
            acc[0][2] += a.x * b.z; acc[0][3] += a.x * b.w;
            acc[1][0] += a.y * b.x; acc[1][1] += a.y * b.y;
            acc[1][2] += a.y * b.z; acc[1][3] += a.y * b.w;
            acc[2][0] += a.z * b.x; acc[2][1] += a.z * b.y;
            acc[2][2] += a.z * b.z; acc[2][3] += a.z * b.w;
            acc[3][0] += a.w * b.x; acc[3][1] += a.w * b.y;
            acc[3][2] += a.w * b.z; acc[3][3] += a.w * b.w;
        }
    }

    #pragma unroll
    for (int i = 0; i < 4; ++i) {
        int grow = row0 + 4 * ty + i;
        if (grow < N_NODES) {
            __half2 h01 = __floats2half2_rn(acc[i][0], acc[i][1]);
            __half2 h23 = __floats2half2_rn(acc[i][2], acc[i][3]);
            uint2 u = make_uint2(*reinterpret_cast<unsigned*>(&h01),
                                 *reinterpret_cast<unsigned*>(&h23));
            *(uint2*)(g_Xl16 + (size_t)grow * OUT_DIM + 4 * tx) = u;
        }
    }
}

// ---------------------------------------------------------------------------
// Gather 1: Xe[e] = (sum Xl[v]) * degE[e] * W_edge[e].  fp16 in/out, fp32 acc.
// 8 threads/edge; replicated segments are contiguous: [off[e*RA], off[(e+1)*RA]).
// ---------------------------------------------------------------------------
__global__ __launch_bounds__(256) void k_gatherA(const float* __restrict__ degE,
                                                 const float* __restrict__ W_edge) {
    int t = blockIdx.x * blockDim.x + threadIdx.x;
    int e = t >> 3;
    if (e >= N_EDGES) return;
    int lane = t & 7;
    int c = lane << 3;

    if (lane < RA) g_cnt[e * RA + lane] = 0;   // reset for next replay

    int beg = g_off[e * RA];
    int end = g_off[(e + 1) * RA];

    float a0 = 0.f, a1 = 0.f, a2 = 0.f, a3 = 0.f;
    float a4 = 0.f, a5 = 0.f, a6 = 0.f, a7 = 0.f;
    #pragma unroll 4
    for (int j = beg; j < end; ++j) {
        int v = __ldg(&g_permA[j]);
        uint4 u = *(const uint4*)(g_Xl16 + (size_t)v * OUT_DIM + c);
        float2 f0 = __half22float2(*reinterpret_cast<__half2*>(&u.x));
        float2 f1 = __half22float2(*reinterpret_cast<__half2*>(&u.y));
        float2 f2 = __half22float2(*reinterpret_cast<__half2*>(&u.z));
        float2 f3 = __half22float2(*reinterpret_cast<__half2*>(&u.w));
        a0 += f0.x; a1 += f0.y; a2 += f1.x; a3 += f1.y;
        a4 += f2.x; a5 += f2.y; a6 += f3.x; a7 += f3.y;
    }
    float s = degE[e] * W_edge[e];
    __half2 h0 = __floats2half2_rn(a0 * s, a1 * s);
    __half2 h1 = __floats2half2_rn(a2 * s, a3 * s);
    __half2 h2 = __floats2half2_rn(a4 * s, a5 * s);
    __half2 h3 = __floats2half2_rn(a6 * s, a7 * s);
    uint4 o;
    o.x = *reinterpret_cast<unsigned*>(&h0);
    o.y = *reinterpret_cast<unsigned*>(&h1);
    o.z = *reinterpret_cast<unsigned*>(&h2);
    o.w = *reinterpret_cast<unsigned*>(&h3);
    *(uint4*)(g_Xe16 + (size_t)e * OUT_DIM + c) = o;
}

// ---------------------------------------------------------------------------
// Gather 2: out[v] = (sum Xe[e]) * degV[v].  fp16 in, fp32 out.
// ---------------------------------------------------------------------------
__global__ __launch_bounds__(256) void k_gatherB(const float* __restrict__ degV,
                                                 float* __restrict__ out) {
    int t = blockIdx.x * blockDim.x + threadIdx.x;
    int v = t >> 3;
    if (v >= N_NODES) return;
    int lane = t & 7;
    int c = lane << 3;

    if (lane < RB) g_cnt[EBASE + v * RB + lane] = 0;   // reset for next replay

    int beg = g_off[EBASE + v * RB] - NNZ;
    int end = g_off[EBASE + (v + 1) * RB] - NNZ;

    float a0 = 0.f, a1 = 0.f, a2 = 0.f, a3 = 0.f;
    float a4 = 0.f, a5 = 0.f, a6 = 0.f, a7 = 0.f;
    #pragma unroll 4
    for (int j = beg; j < end; ++j) {
        int e = __ldg(&g_permB[j]);
        uint4 u = *(const uint4*)(g_Xe16 + (size_t)e * OUT_DIM + c);
        float2 f0 = __half22float2(*reinterpret_cast<__half2*>(&u.x));
        float2 f1 = __half22float2(*reinterpret_cast<__half2*>(&u.y));
        float2 f2 = __half22float2(*reinterpret_cast<__half2*>(&u.z));
        float2 f3 = __half22float2(*reinterpret_cast<__half2*>(&u.w));
        a0 += f0.x; a1 += f0.y; a2 += f1.x; a3 += f1.y;
        a4 += f2.x; a5 += f2.y; a6 += f3.x; a7 += f3.y;
    }
    float s = degV[v];
    float* dst = out + (size_t)v * OUT_DIM + c;
    *(float4*)dst       = make_float4(a0 * s, a1 * s, a2 * s, a3 * s);
    *(float4*)(dst + 4) = make_float4(a4 * s, a5 * s, a6 * s, a7 * s);
}

// ---------------------------------------------------------------------------
extern "C" void kernel_launch(void* const* d_in, const int* in_sizes, int n_in,
                              void* d_out, int out_size) {
    const float* X      = (const float*)d_in[0];
    const int*   vertex = (const int*)d_in[1];
    const int*   edges  = (const int*)d_in[2];
    const float* W_lin  = (const float*)d_in[3];
    const float* degE   = (const float*)d_in[4];
    const float* degV   = (const float*)d_in[5];
    const float* W_edge = (const float*)d_in[6];
    float*       out    = (float*)d_out;

    // g_cnt starts zeroed (static init on first run; gathers re-zero it each
    // run so every graph replay sees zeros — identical work every call).
    k_hist<<<(NNZ + 255) / 256, 256>>>(vertex, edges);
    k_scan1<<<NBLK, SCAN_B>>>();
    k_scan23<<<NBLK, SCAN_B>>>();
    k_fill<<<(NNZ + 255) / 256, 256>>>(vertex, edges);
    k_gemm<<<(N_NODES + 63) / 64, 256>>>(X, W_lin);
    k_gatherA<<<(N_EDGES * 8 + 255) / 256, 256>>>(degE, W_edge);
    k_gatherB<<<(N_NODES * 8 + 255) / 256, 256>>>(degV, out);
}